// round 16
// baseline (speedup 1.0000x reference)
#include <cuda_runtime.h>
#include <math.h>

#define BB 4096
#define TT 40
#define NB 4            // batch rows per warp
#define NWARP 8
#define NTHREADS 256
#define NCTA (BB / (NB * NWARP))   // 128

// smem layout (floats)
#define SM_W2   0
#define SM_W3   (SM_W2 + 16384)
#define SM_W1T  (SM_W3 + 16384)
#define SM_WF   (SM_W1T + 9*128)
#define SM_WM   (SM_WF + 128)
#define SM_HD   (SM_WM + 128)
#define SM_FLOATS (SM_HD + NWARP*NB*256)   // 42368 floats = 169472 B

static __device__ __forceinline__ unsigned long long pk2(float x, float y) {
    unsigned long long r;
    asm("mov.b64 %0, {%1, %2};" : "=l"(r) : "f"(x), "f"(y));
    return r;
}
static __device__ __forceinline__ void upk2(unsigned long long v, float& x, float& y) {
    asm("mov.b64 {%0, %1}, %2;" : "=f"(x), "=f"(y) : "l"(v));
}
// d = a*b + d (two packed fp32 lanes)
static __device__ __forceinline__ void ffma2(unsigned long long& d,
                                             unsigned long long a,
                                             unsigned long long b) {
    asm("fma.rn.f32x2 %0, %1, %2, %0;" : "+l"(d) : "l"(a), "l"(b));
}
static __device__ __forceinline__ void fadd2(unsigned long long& d, unsigned long long a) {
    asm("add.rn.f32x2 %0, %0, %1;" : "+l"(d) : "l"(a));
}
// leaky_relu(x, 0.3) == max(x, 0.3x) since 0 < 0.3 < 1
static __device__ __forceinline__ float lk(float x) { return fmaxf(x, 0.3f * x); }

static __device__ __forceinline__ float idm_act(float vel, float dvel, float dx,
                                                float tg, float jam, float maxa,
                                                float inv_dv, float inv_gd) {
    dx = 0.1f + fmaxf(dx, 0.0f);
    float dg = fmaxf(jam + tg * vel + vel * dvel * inv_gd, 0.0f);
    float r  = vel * inv_dv;
    float r2 = r * r;
    float g  = dg * __fdividef(1.0f, dx);
    float a  = maxa * (1.0f - r2 * r2 - g * g);
    return fminf(fmaxf(a, -50.0f), 50.0f);
}

// write {h,h} duplicated activation row (after leaky) for fast packed broadcast reads
static __device__ __forceinline__ void store_hdup(float* hwb, int j0,
                                                  unsigned long long a01,
                                                  unsigned long long a23) {
    float h0, h1, h2, h3;
    upk2(a01, h0, h1);
    upk2(a23, h2, h3);
    h0 = lk(h0); h1 = lk(h1); h2 = lk(h2); h3 = lk(h3);
    ulonglong2 t0, t1;
    t0.x = pk2(h0, h0); t0.y = pk2(h1, h1);
    t1.x = pk2(h2, h2); t1.y = pk2(h3, h3);
    *(ulonglong2*)(hwb + 2 * j0)     = t0;
    *(ulonglong2*)(hwb + 2 * j0 + 4) = t1;
}

// acc[j0..j0+3] = bias + h(128) @ Ws(128x128), for NB batches sharing the weight reads
static __device__ __forceinline__ void layer128(const float* hw, const float* Ws, int j0,
                                                unsigned long long bp01, unsigned long long bp23,
                                                unsigned long long* a01, unsigned long long* a23) {
#pragma unroll
    for (int b = 0; b < NB; b++) { a01[b] = bp01; a23[b] = bp23; }
#pragma unroll 2
    for (int k0 = 0; k0 < 128; k0 += 2) {
        ulonglong2 hp[NB];
#pragma unroll
        for (int b = 0; b < NB; b++)
            hp[b] = *(const ulonglong2*)(hw + b * 256 + 2 * k0);   // {hk,hk,hk1,hk1} broadcast
        ulonglong2 w0 = *(const ulonglong2*)(Ws + k0 * 128 + j0);
        ulonglong2 w1 = *(const ulonglong2*)(Ws + k0 * 128 + 128 + j0);
#pragma unroll
        for (int b = 0; b < NB; b++) {
            ffma2(a01[b], hp[b].x, w0.x);
            ffma2(a23[b], hp[b].x, w0.y);
        }
#pragma unroll
        for (int b = 0; b < NB; b++) {
            ffma2(a01[b], hp[b].y, w1.x);
            ffma2(a23[b], hp[b].y, w1.y);
        }
    }
}

__global__ void __launch_bounds__(NTHREADS, 1)
idm_rollout_kernel(const float* __restrict__ idmp, const float* __restrict__ pb,
                   const float* __restrict__ eh, const float* __restrict__ idm_s,
                   const float* __restrict__ mcs,
                   const float* __restrict__ W1, const float* __restrict__ b1,
                   const float* __restrict__ W2, const float* __restrict__ b2,
                   const float* __restrict__ W3, const float* __restrict__ b3,
                   const float* __restrict__ Wf, const float* __restrict__ bfp,
                   const float* __restrict__ Wm, const float* __restrict__ bmp,
                   const float* __restrict__ smean, const float* __restrict__ svar,
                   float* __restrict__ out) {
    extern __shared__ float smem[];
    float* W2s = smem + SM_W2;
    float* W3s = smem + SM_W3;
    float* W1t = smem + SM_W1T;
    float* Wfs = smem + SM_WF;
    float* Wms = smem + SM_WM;
    float* hd  = smem + SM_HD;

    const int tid = threadIdx.x;

    // ---- stage weights into smem ----
#pragma unroll 1
    for (int i = tid; i < 4096; i += NTHREADS)
        ((float4*)W2s)[i] = __ldg(&((const float4*)W2)[i]);
#pragma unroll 1
    for (int i = tid; i < 4096; i += NTHREADS)
        ((float4*)W3s)[i] = __ldg(&((const float4*)W3)[i]);
#pragma unroll 1
    for (int i = tid; i < 288; i += NTHREADS)
        ((float4*)W1t)[i] = __ldg(&((const float4*)(W1 + 192 * 128))[i]);
    if (tid < 32)       ((float4*)Wfs)[tid]      = __ldg(&((const float4*)Wf)[tid]);
    else if (tid < 64)  ((float4*)Wms)[tid - 32] = __ldg(&((const float4*)Wm)[tid - 32]);
    __syncthreads();

    const int warp = tid >> 5;
    const int lid  = tid & 31;
    const int j0   = lid << 2;                 // this lane owns outputs j0..j0+3
    const int b0   = (blockIdx.x * NWARP + warp) * NB;
    float* hw = hd + warp * (NB * 256);

    // ---- biases as packed pairs ----
    float4 t;
    t = *(const float4*)(b1 + j0);
    unsigned long long b1_01 = pk2(t.x, t.y), b1_23 = pk2(t.z, t.w);
    t = *(const float4*)(b2 + j0);
    unsigned long long b2_01 = pk2(t.x, t.y), b2_23 = pk2(t.z, t.w);
    t = *(const float4*)(b3 + j0);
    unsigned long long b3_01 = pk2(t.x, t.y), b3_23 = pk2(t.z, t.w);
    const float4 wf4 = *(const float4*)(Wfs + j0);
    const float4 wm4 = *(const float4*)(Wms + j0);
    const float bf = __ldg(bfp), bm = __ldg(bmp);

    float mn[6], is[6];
#pragma unroll
    for (int i = 0; i < 6; i++) {
        mn[i] = __ldg(smean + i);
        is[i] = 1.0f / sqrtf(__ldg(svar + i));
    }

    // ---- per-batch IDM parameters ----
    float tg[NB], jam[NB], maxa[NB], inv_dv[NB], inv_gd[NB];
#pragma unroll
    for (int b = 0; b < NB; b++) {
        const float* p = idmp + (size_t)(b0 + b) * 5;
        float desv = __ldg(p), tgv = __ldg(p + 1), jm = __ldg(p + 2);
        float ma = __ldg(p + 3), mi = __ldg(p + 4);
        tg[b] = tgv; jam[b] = jm; maxa[b] = ma;
        inv_dv[b] = 1.0f / desv;
        inv_gd[b] = 1.0f / (2.0f * sqrtf(ma * mi));
    }

    // ---- base = b1 + [pb, eh] @ W1[:192]  (time-invariant) ----
    unsigned long long base01[NB], base23[NB];
#pragma unroll
    for (int b = 0; b < NB; b++) { base01[b] = b1_01; base23[b] = b1_23; }

#pragma unroll 2
    for (int i0 = 0; i0 < 64; i0 += 4) {
        float xs[4][NB];
#pragma unroll
        for (int b = 0; b < NB; b++) {
            float4 xv = __ldg((const float4*)(pb + (size_t)(b0 + b) * 64 + i0));
            xs[0][b] = xv.x; xs[1][b] = xv.y; xs[2][b] = xv.z; xs[3][b] = xv.w;
        }
#pragma unroll
        for (int kk = 0; kk < 4; kk++) {
            ulonglong2 w = *(const ulonglong2*)(W1 + (size_t)(i0 + kk) * 128 + j0);
#pragma unroll
            for (int b = 0; b < NB; b++) {
                unsigned long long hp = pk2(xs[kk][b], xs[kk][b]);
                ffma2(base01[b], hp, w.x);
                ffma2(base23[b], hp, w.y);
            }
        }
    }
#pragma unroll 2
    for (int i0 = 64; i0 < 192; i0 += 4) {
        float xs[4][NB];
#pragma unroll
        for (int b = 0; b < NB; b++) {
            float4 xv = __ldg((const float4*)(eh + (size_t)(b0 + b) * 128 + (i0 - 64)));
            xs[0][b] = xv.x; xs[1][b] = xv.y; xs[2][b] = xv.z; xs[3][b] = xv.w;
        }
#pragma unroll
        for (int kk = 0; kk < 4; kk++) {
            ulonglong2 w = *(const ulonglong2*)(W1 + (size_t)(i0 + kk) * 128 + j0);
#pragma unroll
            for (int b = 0; b < NB; b++) {
                unsigned long long hp = pk2(xs[kk][b], xs[kk][b]);
                ffma2(base01[b], hp, w.x);
                ffma2(base23[b], hp, w.y);
            }
        }
    }

    // ---- rollout state ----
    float v[NB], x[NB];
#pragma unroll
    for (int b = 0; b < NB; b++) {
        const float* sp = idm_s + (size_t)(b0 + b) * TT * 11;
        v[b] = __ldg(sp + 0);
        x[b] = __ldg(sp + 3);
    }

    for (int tt = 0; tt < TT; tt++) {
        // ---- environment features (redundant across lanes; identical values) ----
        float efdv[NB], efdx[NB], emdv[NB], emdx[NB];
        float e[9][NB];
#pragma unroll
        for (int b = 0; b < NB; b++) {
            const float* sp = idm_s + ((size_t)(b0 + b) * TT + tt) * 11;
            float fv = __ldg(sp + 1), mv = __ldg(sp + 2);
            float fx = __ldg(sp + 4), mx = __ldg(sp + 5);
            float mex = __ldg(sp + 10);
            float dvf = v[b] - fv;
            float dxf = fx - x[b];
            float dvm = (v[b] - mv) * mex;
            float dxm = (mx - x[b]) * mex + (1.0f - mex) * 70.0f;
            efdv[b] = dvf; efdx[b] = dxf; emdv[b] = dvm; emdx[b] = dxm;
            e[0][b] = (v[b] - mn[0]) * is[0];
            e[1][b] = (fv   - mn[1]) * is[1];
            e[2][b] = (dvf  - mn[2]) * is[2];
            e[3][b] = (dxf  - mn[3]) * is[3];
            e[4][b] = (dvm  - mn[4]) * is[4];
            e[5][b] = (dxm  - mn[5]) * is[5];
            const float* mp = mcs + ((size_t)(b0 + b) * TT + tt) * 3;
            e[6][b] = __ldg(mp);
            e[7][b] = __ldg(mp + 1);
            e[8][b] = __ldg(mp + 2);
        }

        // ---- layer 1: base + env(9) @ W1tail ----
        unsigned long long a01[NB], a23[NB];
#pragma unroll
        for (int b = 0; b < NB; b++) { a01[b] = base01[b]; a23[b] = base23[b]; }
#pragma unroll
        for (int i = 0; i < 9; i++) {
            ulonglong2 w = *(const ulonglong2*)(W1t + i * 128 + j0);
#pragma unroll
            for (int b = 0; b < NB; b++) {
                unsigned long long hp = pk2(e[i][b], e[i][b]);
                ffma2(a01[b], hp, w.x);
                ffma2(a23[b], hp, w.y);
            }
        }
        __syncwarp();   // previous step's layer-3 reads are done before overwrite
#pragma unroll
        for (int b = 0; b < NB; b++) store_hdup(hw + b * 256, j0, a01[b], a23[b]);
        __syncwarp();

        // ---- layer 2 ----
        layer128(hw, W2s, j0, b2_01, b2_23, a01, a23);
        __syncwarp();
#pragma unroll
        for (int b = 0; b < NB; b++) store_hdup(hw + b * 256, j0, a01[b], a23[b]);
        __syncwarp();

        // ---- layer 3 ----
        layer128(hw, W3s, j0, b3_01, b3_23, a01, a23);

        // ---- heads + attention + IDM + dynamics ----
#pragma unroll
        for (int b = 0; b < NB; b++) {
            float h0, h1, h2, h3;
            upk2(a01[b], h0, h1);
            upk2(a23[b], h2, h3);
            h0 = lk(h0); h1 = lk(h1); h2 = lk(h2); h3 = lk(h3);
            float pf = h0 * wf4.x + h1 * wf4.y + h2 * wf4.z + h3 * wf4.w;
            float pm = h0 * wm4.x + h1 * wm4.y + h2 * wm4.z + h3 * wm4.w;
            unsigned long long pp = pk2(pf, pm);
#pragma unroll
            for (int off = 16; off > 0; off >>= 1) {
                unsigned long long q = __shfl_xor_sync(0xffffffffu, pp, off);
                fadd2(pp, q);
            }
            float lf, lm;
            upk2(pp, lf, lm);
            lf += bf; lm += bm;
            float fs  = __expf(5.0f * lf);
            float ms2 = __expf(5.0f * lm);
            float rcp = __fdividef(1.0f, fs + ms2);
            float fatt = fs * rcp, matt = ms2 * rcp;
            float efa = idm_act(v[b], efdv[b], efdx[b], tg[b], jam[b], maxa[b], inv_dv[b], inv_gd[b]);
            float ema = idm_act(v[b], emdv[b], emdx[b], tg[b], jam[b], maxa[b], inv_dv[b], inv_gd[b]);
            float act = fatt * efa + matt * ema;
            v[b] = v[b] + act * 0.1f;
            x[b] = x[b] + v[b] * 0.1f + act * 0.005f;
            if (lid == b) {
                int o = (b0 + b) * TT + tt;
                out[o]              = fminf(fmaxf(act, -5.4f), 5.4f);
                out[BB * TT + o]     = fatt;
                out[2 * BB * TT + o] = matt;
            }
        }
    }
}

extern "C" void kernel_launch(void* const* d_in, const int* in_sizes, int n_in,
                              void* d_out, int out_size) {
    const float* idmp = (const float*)d_in[0];
    const float* pb   = (const float*)d_in[1];
    const float* eh   = (const float*)d_in[2];
    const float* s    = (const float*)d_in[3];
    const float* mcs  = (const float*)d_in[4];
    const float* W1   = (const float*)d_in[5];
    const float* b1   = (const float*)d_in[6];
    const float* W2   = (const float*)d_in[7];
    const float* b2   = (const float*)d_in[8];
    const float* W3   = (const float*)d_in[9];
    const float* b3   = (const float*)d_in[10];
    const float* Wf   = (const float*)d_in[11];
    const float* bf   = (const float*)d_in[12];
    const float* Wm   = (const float*)d_in[13];
    const float* bm   = (const float*)d_in[14];
    const float* smn  = (const float*)d_in[15];
    const float* svr  = (const float*)d_in[16];

    const int smem_bytes = SM_FLOATS * (int)sizeof(float);   // 169472
    cudaFuncSetAttribute(idm_rollout_kernel,
                         cudaFuncAttributeMaxDynamicSharedMemorySize, smem_bytes);
    idm_rollout_kernel<<<NCTA, NTHREADS, smem_bytes>>>(
        idmp, pb, eh, s, mcs, W1, b1, W2, b2, W3, b3,
        Wf, bf, Wm, bm, smn, svr, (float*)d_out);
}